// round 1
// baseline (speedup 1.0000x reference)
#include <cuda_runtime.h>

#define N   16384
#define C   64
#define KNN 16
#define O   256       // C*R = 64*4
#define TJ  128       // j-tile per block iteration
#define PITCH 68      // floats; 68 % 32 == 4 -> conflict-free float4 LDS

__device__ float g_sq[N];
__device__ float g_A[N * O];
__device__ float g_B[N * O];
__device__ int   g_idx[N * KNN];

// ---------------------------------------------------------------------------
// squared norms: one warp per row
// ---------------------------------------------------------------------------
__global__ void sq_kernel(const float* __restrict__ x) {
    int row  = blockIdx.x * 8 + (threadIdx.x >> 5);
    int lane = threadIdx.x & 31;
    float v0 = x[row * C + lane];
    float v1 = x[row * C + 32 + lane];
    float s  = v0 * v0 + v1 * v1;
    #pragma unroll
    for (int off = 16; off; off >>= 1)
        s += __shfl_down_sync(0xffffffffu, s, off);
    if (lane == 0) g_sq[row] = s;
}

// ---------------------------------------------------------------------------
// A = x @ (W_top - W_bot) + b ;  B = x @ W_bot
// one block per point n; thread o computes output channel o
// ---------------------------------------------------------------------------
__global__ void ab_kernel(const float* __restrict__ x,
                          const float* __restrict__ W,
                          const float* __restrict__ b) {
    __shared__ float xs[C];
    int n = blockIdx.x;
    int o = threadIdx.x;
    if (o < C) xs[o] = x[n * C + o];
    __syncthreads();
    float accA = b[o];
    float accB = 0.f;
    #pragma unroll
    for (int c = 0; c < C; c++) {
        float wt = W[c * O + o];
        float wb = W[(c + C) * O + o];
        float xv = xs[c];
        accA = fmaf(xv, wt - wb, accA);
        accB = fmaf(xv, wb, accB);
    }
    g_A[n * O + o] = accA;
    g_B[n * O + o] = accB;
}

// ---------------------------------------------------------------------------
// fused distance-tile + per-row top-16.
// 8 warps/block, 1 row per warp, stream 128-j tiles through shared memory.
// key = sq_j - 2 * <x_i, x_j>   (sq_i constant per row -> dropped)
// ---------------------------------------------------------------------------
__global__ __launch_bounds__(256) void knn_kernel(const float* __restrict__ x) {
    __shared__ __align__(16) float XJ[TJ * PITCH];
    __shared__ __align__(16) float XI[8 * PITCH];
    __shared__ float SQ[TJ];

    const int w    = threadIdx.x >> 5;
    const int lane = threadIdx.x & 31;
    const int row  = blockIdx.x * 8 + w;

    // stage this warp's query row
    XI[w * PITCH + lane]      = x[row * C + lane];
    XI[w * PITCH + 32 + lane] = x[row * C + 32 + lane];

    float kd[KNN];
    int   ki[KNN];
    #pragma unroll
    for (int t = 0; t < KNN; t++) { kd[t] = 3.4e38f; ki[t] = -1; }
    float cmax = 3.4e38f;
    int   cpos = 0;

    for (int jt = 0; jt < N; jt += TJ) {
        __syncthreads();
        // cooperative tile load: 128 rows x 64 floats, float4, swizzle-free pitch
        const float4* xg = (const float4*)(x + (size_t)jt * C);
        #pragma unroll
        for (int it = 0; it < 8; it++) {
            int linear = threadIdx.x + 256 * it;   // 0..2047 float4s
            int j  = linear >> 4;                  // 16 float4 per row
            int c4 = linear & 15;
            float4 v = xg[j * 16 + c4];
            *((float4*)&XJ[j * PITCH + c4 * 4]) = v;
        }
        if (threadIdx.x < TJ) SQ[threadIdx.x] = g_sq[jt + threadIdx.x];
        __syncthreads();

        float acc0 = 0.f, acc1 = 0.f, acc2 = 0.f, acc3 = 0.f;
        #pragma unroll
        for (int c4 = 0; c4 < 16; c4++) {
            float4 xi4 = *((const float4*)&XI[w * PITCH + c4 * 4]);
            float4 a = *((const float4*)&XJ[(lane +  0) * PITCH + c4 * 4]);
            float4 b = *((const float4*)&XJ[(lane + 32) * PITCH + c4 * 4]);
            float4 c = *((const float4*)&XJ[(lane + 64) * PITCH + c4 * 4]);
            float4 d = *((const float4*)&XJ[(lane + 96) * PITCH + c4 * 4]);
            acc0 = fmaf(xi4.x, a.x, fmaf(xi4.y, a.y, fmaf(xi4.z, a.z, fmaf(xi4.w, a.w, acc0))));
            acc1 = fmaf(xi4.x, b.x, fmaf(xi4.y, b.y, fmaf(xi4.z, b.z, fmaf(xi4.w, b.w, acc1))));
            acc2 = fmaf(xi4.x, c.x, fmaf(xi4.y, c.y, fmaf(xi4.z, c.z, fmaf(xi4.w, c.w, acc2))));
            acc3 = fmaf(xi4.x, d.x, fmaf(xi4.y, d.y, fmaf(xi4.z, d.z, fmaf(xi4.w, d.w, acc3))));
        }

        #pragma unroll
        for (int q = 0; q < 4; q++) {
            float acc = (q == 0) ? acc0 : (q == 1) ? acc1 : (q == 2) ? acc2 : acc3;
            int   j   = jt + lane + 32 * q;
            float key = fmaf(-2.f, acc, SQ[lane + 32 * q]);
            if (j == row) key = 3.4e38f;          // exclude self
            if (key < cmax) {
                #pragma unroll
                for (int t = 0; t < KNN; t++)
                    if (t == cpos) { kd[t] = key; ki[t] = j; }
                cmax = kd[0]; cpos = 0;
                #pragma unroll
                for (int t = 1; t < KNN; t++)
                    if (kd[t] > cmax) { cmax = kd[t]; cpos = t; }
            }
        }
    }

    // warp-level merge: select 16 smallest of 32 lanes x 16 entries
    const int out_base = row * KNN;
    for (int s = 0; s < KNN; s++) {
        float lm = 3.4e38f; int li = 0x7fffffff; int ls = -1;
        #pragma unroll
        for (int t = 0; t < KNN; t++) {
            bool better = (kd[t] < lm) || (kd[t] == lm && ki[t] < li);
            if (better) { lm = kd[t]; li = ki[t]; ls = t; }
        }
        float m = lm; int mi = li;
        #pragma unroll
        for (int off = 16; off; off >>= 1) {
            float om  = __shfl_down_sync(0xffffffffu, m, off);
            int   omi = __shfl_down_sync(0xffffffffu, mi, off);
            if (om < m || (om == m && omi < mi)) { m = om; mi = omi; }
        }
        m  = __shfl_sync(0xffffffffu, m, 0);
        mi = __shfl_sync(0xffffffffu, mi, 0);
        if (lm == m && li == mi) {                 // winner lane pops its entry
            #pragma unroll
            for (int t = 0; t < KNN; t++)
                if (t == ls) kd[t] = 3.4e38f;
        }
        if (lane == 0) g_idx[out_base + s] = mi;
    }
}

// ---------------------------------------------------------------------------
// out[n, o] = relu(A[n,o] + max_k B[idx[n,k], o]) ; permuted store
// y[(n*4 + r)*64 + c] with o = c*4 + r
// ---------------------------------------------------------------------------
__global__ void out_kernel(float* __restrict__ y) {
    __shared__ int idxs[KNN];
    int n = blockIdx.x;
    int o = threadIdx.x;
    if (o < KNN) idxs[o] = g_idx[n * KNN + o];
    __syncthreads();
    float m = -3.4e38f;
    #pragma unroll
    for (int k = 0; k < KNN; k++)
        m = fmaxf(m, g_B[idxs[k] * O + o]);
    float v = fmaxf(g_A[n * O + o] + m, 0.f);
    y[(n * 4 + (o & 3)) * C + (o >> 2)] = v;
}

// ---------------------------------------------------------------------------
extern "C" void kernel_launch(void* const* d_in, const int* in_sizes, int n_in,
                              void* d_out, int out_size) {
    const float* x = (const float*)d_in[0];
    const float* W = (const float*)d_in[1];
    const float* b = (const float*)d_in[2];
    float* y = (float*)d_out;

    sq_kernel <<<N / 8, 256>>>(x);
    ab_kernel <<<N, 256>>>(x, W, b);
    knn_kernel<<<N / 8, 256>>>(x);
    out_kernel<<<N, 256>>>(y);
}

// round 7
// speedup vs baseline: 1.3607x; 1.3607x over previous
#include <cuda_runtime.h>

#define N     16384
#define C     64
#define KNN   16
#define O     256       // C*R
#define TJ    128       // j-tile rows
#define PITCH 68        // floats; stride 272B -> 16B aligned, conflict-free float4
#define QW    4         // queries per warp
#define CAP   12        // per-lane candidate list size
#define NB    32        // points per block in ab_kernel
#define FINF  3.4e38f

__device__ float g_sq[N];
__device__ float g_A[N * O];
__device__ float g_B[N * O];
__device__ int   g_idx[N * KNN];

// ---------------------------------------------------------------------------
// squared norms: one warp per row
// ---------------------------------------------------------------------------
__global__ void sq_kernel(const float* __restrict__ x) {
    int row  = blockIdx.x * 8 + (threadIdx.x >> 5);
    int lane = threadIdx.x & 31;
    float v0 = x[row * C + lane];
    float v1 = x[row * C + 32 + lane];
    float s  = v0 * v0 + v1 * v1;
    #pragma unroll
    for (int off = 16; off; off >>= 1)
        s += __shfl_down_sync(0xffffffffu, s, off);
    if (lane == 0) g_sq[row] = s;
}

// ---------------------------------------------------------------------------
// A = x @ (W_top - W_bot) + b ;  B = x @ W_bot
// 32 points per block; W streamed once per block.
// ---------------------------------------------------------------------------
__global__ __launch_bounds__(256) void ab_kernel(const float* __restrict__ x,
                                                 const float* __restrict__ W,
                                                 const float* __restrict__ b) {
    __shared__ float xs[NB][C + 1];
    const int o  = threadIdx.x;
    const int nb = blockIdx.x * NB;
    #pragma unroll
    for (int it = 0; it < (NB * C) / 256; it++) {
        int linear = threadIdx.x + 256 * it;
        xs[linear >> 6][linear & 63] = x[nb * C + linear];
    }
    __syncthreads();
    float accA[NB], accB[NB];
    float bb = b[o];
    #pragma unroll
    for (int i = 0; i < NB; i++) { accA[i] = bb; accB[i] = 0.f; }
    for (int c = 0; c < C; c++) {
        float wt = W[c * O + o];
        float wb = W[(c + C) * O + o];
        float wd = wt - wb;
        #pragma unroll
        for (int i = 0; i < NB; i++) {
            float xv = xs[i][c];
            accA[i] = fmaf(xv, wd, accA[i]);
            accB[i] = fmaf(xv, wb, accB[i]);
        }
    }
    #pragma unroll
    for (int i = 0; i < NB; i++) {
        g_A[(nb + i) * O + o] = accA[i];
        g_B[(nb + i) * O + o] = accB[i];
    }
}

// ---------------------------------------------------------------------------
// fused distance + top-16, 4 queries per warp, plain float4/fmaf (no asm).
// key = sq_j - 2 * <x_i, x_j>   (sq_i constant per row -> dropped)
// ---------------------------------------------------------------------------
__global__ __launch_bounds__(256) void knn_kernel(const float* __restrict__ x) {
    __shared__ __align__(16) float XJ[TJ * PITCH];   // 34816 B
    __shared__ __align__(16) float XI[32 * PITCH];   //  8704 B
    __shared__ float SQ[TJ];

    const int w       = threadIdx.x >> 5;
    const int lane    = threadIdx.x & 31;
    const int rowBase = blockIdx.x * 32 + w * QW;

    // stage this block's 32 query rows
    {
        const float4* xg = (const float4*)(x + (size_t)blockIdx.x * 32 * C);
        #pragma unroll
        for (int it = 0; it < 2; it++) {
            int linear = threadIdx.x + 256 * it;      // 0..511 float4s
            int r  = linear >> 4;
            int c4 = linear & 15;
            *((float4*)&XI[r * PITCH + c4 * 4]) = xg[r * 16 + c4];
        }
    }

    float kd[QW][CAP]; int ki[QW][CAP];
    float cmax[QW]; int cpos[QW];
    #pragma unroll
    for (int q = 0; q < QW; q++) {
        #pragma unroll
        for (int t = 0; t < CAP; t++) { kd[q][t] = FINF; ki[q][t] = 0x7fffffff; }
        cmax[q] = FINF; cpos[q] = 0;
    }

    for (int jt = 0; jt < N; jt += TJ) {
        __syncthreads();
        const float4* xg = (const float4*)(x + (size_t)jt * C);
        #pragma unroll
        for (int it = 0; it < 8; it++) {
            int linear = threadIdx.x + 256 * it;      // 0..2047 float4s
            int j  = linear >> 4;
            int c4 = linear & 15;
            *((float4*)&XJ[j * PITCH + c4 * 4]) = xg[j * 16 + c4];
        }
        if (threadIdx.x < TJ) SQ[threadIdx.x] = g_sq[jt + threadIdx.x];
        __syncthreads();

        float acc[QW][4];
        #pragma unroll
        for (int q = 0; q < QW; q++)
            #pragma unroll
            for (int g = 0; g < 4; g++) acc[q][g] = 0.f;

        #pragma unroll
        for (int c4 = 0; c4 < 16; c4++) {
            float4 xi4[QW];
            #pragma unroll
            for (int q = 0; q < QW; q++)            // broadcast reads
                xi4[q] = *((const float4*)&XI[(w * QW + q) * PITCH + c4 * 4]);
            #pragma unroll
            for (int g = 0; g < 4; g++) {
                float4 a = *((const float4*)&XJ[(lane + 32 * g) * PITCH + c4 * 4]);
                #pragma unroll
                for (int q = 0; q < QW; q++) {
                    float s = acc[q][g];
                    s = fmaf(xi4[q].x, a.x, s);
                    s = fmaf(xi4[q].y, a.y, s);
                    s = fmaf(xi4[q].z, a.z, s);
                    s = fmaf(xi4[q].w, a.w, s);
                    acc[q][g] = s;
                }
            }
        }

        #pragma unroll
        for (int q = 0; q < QW; q++) {
            #pragma unroll
            for (int g = 0; g < 4; g++) {
                int   j   = jt + lane + 32 * g;
                float key = fmaf(-2.f, acc[q][g], SQ[lane + 32 * g]);
                if (j == rowBase + q) key = FINF;         // exclude self
                if (key < cmax[q]) {
                    #pragma unroll
                    for (int t = 0; t < CAP; t++)
                        if (t == cpos[q]) { kd[q][t] = key; ki[q][t] = j; }
                    cmax[q] = kd[q][0]; cpos[q] = 0;
                    #pragma unroll
                    for (int t = 1; t < CAP; t++)
                        if (kd[q][t] > cmax[q]) { cmax[q] = kd[q][t]; cpos[q] = t; }
                }
            }
        }
    }

    // warp merge: 16 smallest across 32 lanes x CAP entries, per query
    #pragma unroll
    for (int q = 0; q < QW; q++) {
        const int out_base = (rowBase + q) * KNN;
        for (int s = 0; s < KNN; s++) {
            float lm = FINF; int li = 0x7fffffff; int ls = -1;
            #pragma unroll
            for (int t = 0; t < CAP; t++) {
                bool better = (kd[q][t] < lm) || (kd[q][t] == lm && ki[q][t] < li);
                if (better) { lm = kd[q][t]; li = ki[q][t]; ls = t; }
            }
            float m = lm; int mi = li;
            #pragma unroll
            for (int off = 16; off; off >>= 1) {
                float om  = __shfl_down_sync(0xffffffffu, m, off);
                int   omi = __shfl_down_sync(0xffffffffu, mi, off);
                if (om < m || (om == m && omi < mi)) { m = om; mi = omi; }
            }
            m  = __shfl_sync(0xffffffffu, m, 0);
            mi = __shfl_sync(0xffffffffu, mi, 0);
            if (lm == m && li == mi) {
                #pragma unroll
                for (int t = 0; t < CAP; t++)
                    if (t == ls) { kd[q][t] = FINF; ki[q][t] = 0x7fffffff; }
            }
            if (lane == 0) g_idx[out_base + s] = mi;
        }
    }
}

// ---------------------------------------------------------------------------
// out[n, o] = relu(A[n,o] + max_k B[idx[n,k], o]) ; permuted store
// ---------------------------------------------------------------------------
__global__ void out_kernel(float* __restrict__ y) {
    __shared__ int idxs[KNN];
    int n = blockIdx.x;
    int o = threadIdx.x;
    if (o < KNN) idxs[o] = g_idx[n * KNN + o];
    __syncthreads();
    float m = -FINF;
    #pragma unroll
    for (int k = 0; k < KNN; k++)
        m = fmaxf(m, g_B[idxs[k] * O + o]);
    float v = fmaxf(g_A[n * O + o] + m, 0.f);
    y[(n * 4 + (o & 3)) * C + (o >> 2)] = v;
}

// ---------------------------------------------------------------------------
extern "C" void kernel_launch(void* const* d_in, const int* in_sizes, int n_in,
                              void* d_out, int out_size) {
    const float* x = (const float*)d_in[0];
    const float* W = (const float*)d_in[1];
    const float* b = (const float*)d_in[2];
    float* y = (float*)d_out;

    sq_kernel <<<N / 8, 256>>>(x);
    knn_kernel<<<N / 32, 256>>>(x);
    ab_kernel <<<N / NB, 256>>>(x, W, b);
    out_kernel<<<N, 256>>>(y);
}

// round 8
// speedup vs baseline: 2.4784x; 1.8215x over previous
#include <cuda_runtime.h>

#define N     16384
#define C     64
#define KNN   16
#define O     256       // C*R
#define TJ    128       // j-tile rows
#define PITCH 68        // floats; stride 272B -> 16B aligned, conflict-free float4
#define QW    4         // queries per warp
#define NB    32        // points per block in ab_kernel
#define FINF  3.4e38f
#define FULLM 0xffffffffu

__device__ float g_sq[N];
__device__ float g_A[N * O];
__device__ float g_B[N * O];
__device__ int   g_idx[N * KNN];

// ---------------------------------------------------------------------------
// squared norms: one warp per row
// ---------------------------------------------------------------------------
__global__ void sq_kernel(const float* __restrict__ x) {
    int row  = blockIdx.x * 8 + (threadIdx.x >> 5);
    int lane = threadIdx.x & 31;
    float v0 = x[row * C + lane];
    float v1 = x[row * C + 32 + lane];
    float s  = v0 * v0 + v1 * v1;
    #pragma unroll
    for (int off = 16; off; off >>= 1)
        s += __shfl_down_sync(FULLM, s, off);
    if (lane == 0) g_sq[row] = s;
}

// ---------------------------------------------------------------------------
// A = x @ (W_top - W_bot) + b ;  B = x @ W_bot
// ---------------------------------------------------------------------------
__global__ __launch_bounds__(256) void ab_kernel(const float* __restrict__ x,
                                                 const float* __restrict__ W,
                                                 const float* __restrict__ b) {
    __shared__ float xs[NB][C + 1];
    const int o  = threadIdx.x;
    const int nb = blockIdx.x * NB;
    #pragma unroll
    for (int it = 0; it < (NB * C) / 256; it++) {
        int linear = threadIdx.x + 256 * it;
        xs[linear >> 6][linear & 63] = x[nb * C + linear];
    }
    __syncthreads();
    float accA[NB], accB[NB];
    float bb = b[o];
    #pragma unroll
    for (int i = 0; i < NB; i++) { accA[i] = bb; accB[i] = 0.f; }
    for (int c = 0; c < C; c++) {
        float wt = W[c * O + o];
        float wb = W[(c + C) * O + o];
        float wd = wt - wb;
        #pragma unroll
        for (int i = 0; i < NB; i++) {
            float xv = xs[i][c];
            accA[i] = fmaf(xv, wd, accA[i]);
            accB[i] = fmaf(xv, wb, accB[i]);
        }
    }
    #pragma unroll
    for (int i = 0; i < NB; i++) {
        g_A[(nb + i) * O + o] = accA[i];
        g_B[(nb + i) * O + o] = accB[i];
    }
}

// ---------------------------------------------------------------------------
// fused distance + top-16, warp-cooperative shared-memory top-k.
// key = sq_j - 2 * <x_i, x_j>   (sq_i constant per row -> dropped)
// ---------------------------------------------------------------------------
__global__ __launch_bounds__(256, 2) void knn_kernel(const float* __restrict__ x) {
    __shared__ __align__(16) float XJ[TJ * PITCH];   // 34816 B
    __shared__ __align__(16) float XI[32 * PITCH];   //  8704 B
    __shared__ float SQ[TJ];                          //   512 B
    __shared__ float LK[32][KNN];                     //  2048 B
    __shared__ int   LI[32][KNN];                     //  2048 B

    const int w       = threadIdx.x >> 5;
    const int lane    = threadIdx.x & 31;
    const int rowBase = blockIdx.x * 32 + w * QW;
    const int t16     = lane & 15;

    // stage this block's 32 query rows
    {
        const float4* xg = (const float4*)(x + (size_t)blockIdx.x * 32 * C);
        #pragma unroll
        for (int it = 0; it < 2; it++) {
            int linear = threadIdx.x + 256 * it;      // 0..511 float4s
            int r  = linear >> 4;
            int c4 = linear & 15;
            *((float4*)&XI[r * PITCH + c4 * 4]) = xg[r * 16 + c4];
        }
    }
    // init this warp's 4 top-k lists
    if (lane < KNN) {
        #pragma unroll
        for (int q = 0; q < QW; q++) {
            LK[w * QW + q][lane] = FINF;
            LI[w * QW + q][lane] = 0;
        }
    }
    float cm[QW];
    #pragma unroll
    for (int q = 0; q < QW; q++) cm[q] = FINF;

    for (int jt = 0; jt < N; jt += TJ) {
        __syncthreads();
        const float4* xg = (const float4*)(x + (size_t)jt * C);
        #pragma unroll
        for (int it = 0; it < 8; it++) {
            int linear = threadIdx.x + 256 * it;      // 0..2047 float4s
            int j  = linear >> 4;
            int c4 = linear & 15;
            *((float4*)&XJ[j * PITCH + c4 * 4]) = xg[j * 16 + c4];
        }
        if (threadIdx.x < TJ) SQ[threadIdx.x] = g_sq[jt + threadIdx.x];
        __syncthreads();

        float acc[QW][4];
        #pragma unroll
        for (int q = 0; q < QW; q++)
            #pragma unroll
            for (int g = 0; g < 4; g++) acc[q][g] = 0.f;

        #pragma unroll
        for (int c4 = 0; c4 < 16; c4++) {
            float4 xi4[QW];
            #pragma unroll
            for (int q = 0; q < QW; q++)            // broadcast reads
                xi4[q] = *((const float4*)&XI[(w * QW + q) * PITCH + c4 * 4]);
            #pragma unroll
            for (int g = 0; g < 4; g++) {
                float4 a = *((const float4*)&XJ[(lane + 32 * g) * PITCH + c4 * 4]);
                #pragma unroll
                for (int q = 0; q < QW; q++) {
                    float s = acc[q][g];
                    s = fmaf(xi4[q].x, a.x, s);
                    s = fmaf(xi4[q].y, a.y, s);
                    s = fmaf(xi4[q].z, a.z, s);
                    s = fmaf(xi4[q].w, a.w, s);
                    acc[q][g] = s;
                }
            }
        }

        #pragma unroll
        for (int q = 0; q < QW; q++) {
            const int qq = w * QW + q;
            float key[4];
            #pragma unroll
            for (int g = 0; g < 4; g++) {
                key[g] = fmaf(-2.f, acc[q][g], SQ[lane + 32 * g]);
                if (jt + lane + 32 * g == rowBase + q) key[g] = FINF;  // self
            }
            float kmin = fminf(fminf(key[0], key[1]), fminf(key[2], key[3]));
            if (__ballot_sync(FULLM, kmin < cm[q])) {
                #pragma unroll
                for (int g = 0; g < 4; g++) {
                    unsigned b = __ballot_sync(FULLM, key[g] < cm[q]);
                    while (b) {
                        int src = __ffs(b) - 1;
                        b &= b - 1;
                        float ck = __shfl_sync(FULLM, key[g], src);
                        int   cj = jt + src + 32 * g;
                        if (ck < cm[q]) {            // re-check vs updated cm
                            // warp-parallel argmax over the 16-entry list
                            float lv = (lane < KNN) ? LK[qq][t16] : -FINF;
                            int   lp = t16;
                            #pragma unroll
                            for (int off = 8; off; off >>= 1) {
                                float ov = __shfl_xor_sync(FULLM, lv, off);
                                int   op = __shfl_xor_sync(FULLM, lp, off);
                                if (ov > lv || (ov == lv && op < lp)) { lv = ov; lp = op; }
                            }
                            int mp = __shfl_sync(FULLM, lp, 0);
                            if (lane == 0) { LK[qq][mp] = ck; LI[qq][mp] = cj; }
                            __syncwarp(FULLM);
                            // recompute running 16th-max threshold
                            float nv = (lane < KNN) ? LK[qq][t16] : -FINF;
                            #pragma unroll
                            for (int off = 8; off; off >>= 1)
                                nv = fmaxf(nv, __shfl_xor_sync(FULLM, nv, off));
                            cm[q] = __shfl_sync(FULLM, nv, 0);
                        }
                    }
                }
            }
        }
    }

    // write out the lists (order within 16 is irrelevant: feeds a max-pool)
    __syncwarp(FULLM);
    if (lane < KNN) {
        #pragma unroll
        for (int q = 0; q < QW; q++)
            g_idx[(rowBase + q) * KNN + lane] = LI[w * QW + q][lane];
    }
}

// ---------------------------------------------------------------------------
// out[n, o] = relu(A[n,o] + max_k B[idx[n,k], o]) ; permuted store
// ---------------------------------------------------------------------------
__global__ void out_kernel(float* __restrict__ y) {
    __shared__ int idxs[KNN];
    int n = blockIdx.x;
    int o = threadIdx.x;
    if (o < KNN) idxs[o] = g_idx[n * KNN + o];
    __syncthreads();
    float m = -FINF;
    #pragma unroll
    for (int k = 0; k < KNN; k++)
        m = fmaxf(m, g_B[idxs[k] * O + o]);
    float v = fmaxf(g_A[n * O + o] + m, 0.f);
    y[(n * 4 + (o & 3)) * C + (o >> 2)] = v;
}

// ---------------------------------------------------------------------------
extern "C" void kernel_launch(void* const* d_in, const int* in_sizes, int n_in,
                              void* d_out, int out_size) {
    const float* x = (const float*)d_in[0];
    const float* W = (const float*)d_in[1];
    const float* b = (const float*)d_in[2];
    float* y = (float*)d_out;

    sq_kernel <<<N / 8, 256>>>(x);
    knn_kernel<<<N / 32, 256>>>(x);
    ab_kernel <<<N / NB, 256>>>(x, W, b);
    out_kernel<<<N, 256>>>(y);
}

// round 11
// speedup vs baseline: 3.1796x; 1.2829x over previous
#include <cuda_runtime.h>
#include <cuda_fp16.h>
#include <mma.h>

using namespace nvcuda;

#define N     16384
#define C     64
#define KNN   16
#define O     256       // C*R
#define QB    64        // queries per block
#define TJ    64        // j-tile rows
#define NB    32        // points per block in ab_kernel
#define FINF  3.4e38f
#define FULLM 0xffffffffu

#define BP    72        // half pitch for B/A-stage tiles (144B rows)
#define DP    68        // float pitch for D tile

__device__ float g_sq[N];
__device__ __half g_hi[N * C];
__device__ __half g_lo[N * C];
__device__ float g_A[N * O];
__device__ float g_B[N * O];
__device__ int   g_idx[N * KNN];

// ---------------------------------------------------------------------------
// squared norms + fp16 hi/lo split: one warp per row
// ---------------------------------------------------------------------------
__global__ void sq_kernel(const float* __restrict__ x) {
    int row  = blockIdx.x * 8 + (threadIdx.x >> 5);
    int lane = threadIdx.x & 31;
    float v0 = x[row * C + lane];
    float v1 = x[row * C + 32 + lane];

    __half h0 = __float2half_rn(v0);
    __half h1 = __float2half_rn(v1);
    g_hi[row * C + lane]      = h0;
    g_hi[row * C + 32 + lane] = h1;
    g_lo[row * C + lane]      = __float2half_rn(v0 - __half2float(h0));
    g_lo[row * C + 32 + lane] = __float2half_rn(v1 - __half2float(h1));

    float s = v0 * v0 + v1 * v1;
    #pragma unroll
    for (int off = 16; off; off >>= 1)
        s += __shfl_down_sync(FULLM, s, off);
    if (lane == 0) g_sq[row] = s;
}

// ---------------------------------------------------------------------------
// A = x @ (W_top - W_bot) + b ;  B = x @ W_bot
// ---------------------------------------------------------------------------
__global__ __launch_bounds__(256) void ab_kernel(const float* __restrict__ x,
                                                 const float* __restrict__ W,
                                                 const float* __restrict__ b) {
    __shared__ float xs[NB][C + 1];
    const int o  = threadIdx.x;
    const int nb = blockIdx.x * NB;
    #pragma unroll
    for (int it = 0; it < (NB * C) / 256; it++) {
        int linear = threadIdx.x + 256 * it;
        xs[linear >> 6][linear & 63] = x[nb * C + linear];
    }
    __syncthreads();
    float accA[NB], accB[NB];
    float bb = b[o];
    #pragma unroll
    for (int i = 0; i < NB; i++) { accA[i] = bb; accB[i] = 0.f; }
    for (int c = 0; c < C; c++) {
        float wt = W[c * O + o];
        float wb = W[(c + C) * O + o];
        float wd = wt - wb;
        #pragma unroll
        for (int i = 0; i < NB; i++) {
            float xv = xs[i][c];
            accA[i] = fmaf(xv, wd, accA[i]);
            accB[i] = fmaf(xv, wb, accB[i]);
        }
    }
    #pragma unroll
    for (int i = 0; i < NB; i++) {
        g_A[(nb + i) * O + o] = accA[i];
        g_B[(nb + i) * O + o] = accB[i];
    }
}

// ---------------------------------------------------------------------------
// tensor-core knn: D = Xq @ Xj^T via fp16 split (hi*hi + hi*lo + lo*hi),
// fp32 accumulate; warp-cooperative exact top-16 per query.
// key = sq_j - 2*dot   (sq_i constant per row -> dropped)
// 512 threads = 16 warps; warp w owns GEMM tile (mt = w>>2, nt = w&3)
// and selection for queries [w*4, w*4+4).
// ---------------------------------------------------------------------------
__global__ __launch_bounds__(512, 1) void knn_kernel(const float* __restrict__ x) {
    __shared__ __align__(16) __half BH[TJ][BP];     //  9216 B
    __shared__ __align__(16) __half BL[TJ][BP];     //  9216 B
    __shared__ __align__(16) float  Dsh[QB][DP];    // 17408 B (A-stage in prologue)
    __shared__ float SQt[TJ];
    __shared__ float LK[QB][KNN];                   //  4096 B
    __shared__ int   LI[QB][KNN];                   //  4096 B

    const int tid  = threadIdx.x;
    const int w    = tid >> 5;
    const int lane = tid & 31;
    const int mt   = w >> 2;          // 0..3  (m-tile: 16 queries)
    const int nt   = w & 3;           // 0..3  (n-tile: 16 j's)
    const int qBase = blockIdx.x * QB;
    const int t16  = lane & 15;

    // ---- prologue: stage this block's query rows (hi into Dsh, lo into BH) --
    {
        __half* AH = (__half*)&Dsh[0][0];
        __half* AL = (__half*)&BH[0][0];
        int j  = tid >> 3;            // 0..63
        int k8 = tid & 7;             // 0..7  (8 halves = 16B)
        const uint4* sh = (const uint4*)(g_hi + (size_t)(qBase + j) * C + k8 * 8);
        const uint4* sl = (const uint4*)(g_lo + (size_t)(qBase + j) * C + k8 * 8);
        *((uint4*)(AH + j * BP + k8 * 8)) = *sh;
        *((uint4*)(AL + j * BP + k8 * 8)) = *sl;
    }
    __syncthreads();

    wmma::fragment<wmma::matrix_a, 16, 16, 16, __half, wmma::row_major> a_hi[4], a_lo[4];
    {
        const __half* AH = (const __half*)&Dsh[0][0];
        const __half* AL = (const __half*)&BH[0][0];
        #pragma unroll
        for (int kk = 0; kk < 4; kk++) {
            wmma::load_matrix_sync(a_hi[kk], AH + (mt * 16) * BP + kk * 16, BP);
            wmma::load_matrix_sync(a_lo[kk], AL + (mt * 16) * BP + kk * 16, BP);
        }
    }

    // ---- init top-k lists (warp w owns queries w*4 .. w*4+3) ---------------
    if (lane < KNN) {
        #pragma unroll
        for (int qi = 0; qi < 4; qi++) {
            LK[w * 4 + qi][lane] = FINF;
            LI[w * 4 + qi][lane] = 0;
        }
    }
    float cm[4];
    #pragma unroll
    for (int qi = 0; qi < 4; qi++) cm[qi] = FINF;

    // ---- main loop over j-tiles --------------------------------------------
    for (int jt = 0; jt < N; jt += TJ) {
        __syncthreads();   // D consumed, B free, (iter 0: a-frags loaded)
        {
            int j  = tid >> 3;
            int k8 = tid & 7;
            const uint4* sh = (const uint4*)(g_hi + (size_t)(jt + j) * C + k8 * 8);
            const uint4* sl = (const uint4*)(g_lo + (size_t)(jt + j) * C + k8 * 8);
            *((uint4*)(&BH[j][k8 * 8])) = *sh;
            *((uint4*)(&BL[j][k8 * 8])) = *sl;
        }
        if (tid < TJ) SQt[tid] = g_sq[jt + tid];
        __syncthreads();

        // GEMM: 16x16 tile per warp, 3 split terms x 4 k-steps
        {
            wmma::fragment<wmma::accumulator, 16, 16, 16, float> acc;
            wmma::fill_fragment(acc, 0.f);
            #pragma unroll
            for (int kk = 0; kk < 4; kk++) {
                wmma::fragment<wmma::matrix_b, 16, 16, 16, __half, wmma::col_major> b_hi, b_lo;
                wmma::load_matrix_sync(b_hi, &BH[nt * 16][kk * 16], BP);
                wmma::load_matrix_sync(b_lo, &BL[nt * 16][kk * 16], BP);
                wmma::mma_sync(acc, a_hi[kk], b_hi, acc);
                wmma::mma_sync(acc, a_hi[kk], b_lo, acc);
                wmma::mma_sync(acc, a_lo[kk], b_hi, acc);
            }
            wmma::store_matrix_sync(&Dsh[mt * 16][nt * 16], acc, DP, wmma::mem_row_major);
        }
        __syncthreads();

        // selection: warp w handles queries w*4..w*4+3; lane covers j=lane, lane+32
        #pragma unroll
        for (int qi = 0; qi < 4; qi++) {
            const int q  = w * 4 + qi;
            const int qg = qBase + q;
            float key[2];
            #pragma unroll
            for (int g = 0; g < 2; g++) {
                int jj = lane + 32 * g;
                key[g] = fmaf(-2.f, Dsh[q][jj], SQt[jj]);
                if (jt + jj == qg) key[g] = FINF;      // exclude self
            }
            float kmin = fminf(key[0], key[1]);
            if (__ballot_sync(FULLM, kmin < cm[qi])) {
                #pragma unroll
                for (int g = 0; g < 2; g++) {
                    unsigned bmask = __ballot_sync(FULLM, key[g] < cm[qi]);
                    while (bmask) {
                        int src = __ffs(bmask) - 1;
                        bmask &= bmask - 1;
                        float ck = __shfl_sync(FULLM, key[g], src);
                        int   cj = jt + src + 32 * g;
                        if (ck < cm[qi]) {             // re-check vs updated cm
                            float lv = (lane < KNN) ? LK[q][t16] : -FINF;
                            int   lp = t16;
                            #pragma unroll
                            for (int off = 8; off; off >>= 1) {
                                float ov = __shfl_xor_sync(FULLM, lv, off);
                                int   op = __shfl_xor_sync(FULLM, lp, off);
                                if (ov > lv || (ov == lv && op < lp)) { lv = ov; lp = op; }
                            }
                            int mp = __shfl_sync(FULLM, lp, 0);
                            if (lane == 0) { LK[q][mp] = ck; LI[q][mp] = cj; }
                            __syncwarp(FULLM);
                            float nv = (lane < KNN) ? LK[q][t16] : -FINF;
                            #pragma unroll
                            for (int off = 8; off; off >>= 1)
                                nv = fmaxf(nv, __shfl_xor_sync(FULLM, nv, off));
                            cm[qi] = __shfl_sync(FULLM, nv, 0);
                        }
                    }
                }
            }
        }
    }

    // ---- write out lists (order irrelevant: feeds max-pool) ----------------
    __syncwarp(FULLM);
    if (lane < KNN) {
        #pragma unroll
        for (int qi = 0; qi < 4; qi++)
            g_idx[(qBase + w * 4 + qi) * KNN + lane] = LI[w * 4 + qi][lane];
    }
}

// ---------------------------------------------------------------------------
// out[n, o] = relu(A[n,o] + max_k B[idx[n,k], o]) ; permuted store
// ---------------------------------------------------------------------------
__global__ void out_kernel(float* __restrict__ y) {
    __shared__ int idxs[KNN];
    int n = blockIdx.x;
    int o = threadIdx.x;
    if (o < KNN) idxs[o] = g_idx[n * KNN + o];
    __syncthreads();
    float m = -FINF;
    #pragma unroll
    for (int k = 0; k < KNN; k++)
        m = fmaxf(m, g_B[idxs[k] * O + o]);
    float v = fmaxf(g_A[n * O + o] + m, 0.f);
    y[(n * 4 + (o & 3)) * C + (o >> 2)] = v;
}

// ---------------------------------------------------------------------------
extern "C" void kernel_launch(void* const* d_in, const int* in_sizes, int n_in,
                              void* d_out, int out_size) {
    const float* x = (const float*)d_in[0];
    const float* W = (const float*)d_in[1];
    const float* b = (const float*)d_in[2];
    float* y = (float*)d_out;

    sq_kernel <<<N / 8, 256>>>(x);
    knn_kernel<<<N / QB, 512>>>(x);
    ab_kernel <<<N / NB, 256>>>(x, W, b);
    out_kernel<<<N, 256>>>(y);
}

// round 13
// speedup vs baseline: 3.5213x; 1.1075x over previous
#include <cuda_runtime.h>
#include <cuda_fp16.h>
#include <mma.h>

using namespace nvcuda;

#define N     16384
#define C     64
#define KNN   16
#define O     256       // C*R
#define QB    64        // queries per block
#define TJ    64        // j-tile rows
#define NB    32        // points per block in ab_kernel
#define FINF  3.4e38f
#define FULLM 0xffffffffu

#define BP    72        // half pitch for B/A-stage tiles (144B rows)
#define DP    68        // float pitch for D tile

__device__ float g_sq[N];
__device__ __half g_hi[N * C];    // -2*x (hi part)
__device__ __half g_lo[N * C];    // -2*x (lo part)
__device__ __half g_qhi[N * C];   // +x (hi part)  for the A side
__device__ __half g_qlo[N * C];   // +x (lo part)
__device__ float g_A[N * O];
__device__ float g_B[N * O];
__device__ int   g_idx[N * KNN];

// ---------------------------------------------------------------------------
// squared norms + fp16 hi/lo splits (query side: x ; key side: -2x)
// one warp per row
// ---------------------------------------------------------------------------
__global__ void sq_kernel(const float* __restrict__ x) {
    int row  = blockIdx.x * 8 + (threadIdx.x >> 5);
    int lane = threadIdx.x & 31;
    float s = 0.f;
    #pragma unroll
    for (int h = 0; h < 2; h++) {
        float v = x[row * C + 32 * h + lane];
        __half qh = __float2half_rn(v);
        g_qhi[row * C + 32 * h + lane] = qh;
        g_qlo[row * C + 32 * h + lane] = __float2half_rn(v - __half2float(qh));
        float v2 = -2.f * v;
        __half kh = __float2half_rn(v2);
        g_hi[row * C + 32 * h + lane] = kh;
        g_lo[row * C + 32 * h + lane] = __float2half_rn(v2 - __half2float(kh));
        s += v * v;
    }
    #pragma unroll
    for (int off = 16; off; off >>= 1)
        s += __shfl_down_sync(FULLM, s, off);
    if (lane == 0) g_sq[row] = s;
}

// ---------------------------------------------------------------------------
// A = x @ (W_top - W_bot) + b ;  B = x @ W_bot
// ---------------------------------------------------------------------------
__global__ __launch_bounds__(256) void ab_kernel(const float* __restrict__ x,
                                                 const float* __restrict__ W,
                                                 const float* __restrict__ b) {
    __shared__ float xs[NB][C + 1];
    const int o  = threadIdx.x;
    const int nb = blockIdx.x * NB;
    #pragma unroll
    for (int it = 0; it < (NB * C) / 256; it++) {
        int linear = threadIdx.x + 256 * it;
        xs[linear >> 6][linear & 63] = x[nb * C + linear];
    }
    __syncthreads();
    float accA[NB], accB[NB];
    float bb = b[o];
    #pragma unroll
    for (int i = 0; i < NB; i++) { accA[i] = bb; accB[i] = 0.f; }
    for (int c = 0; c < C; c++) {
        float wt = W[c * O + o];
        float wb = W[(c + C) * O + o];
        float wd = wt - wb;
        #pragma unroll
        for (int i = 0; i < NB; i++) {
            float xv = xs[i][c];
            accA[i] = fmaf(xv, wd, accA[i]);
            accB[i] = fmaf(xv, wb, accB[i]);
        }
    }
    #pragma unroll
    for (int i = 0; i < NB; i++) {
        g_A[(nb + i) * O + o] = accA[i];
        g_B[(nb + i) * O + o] = accB[i];
    }
}

// ---------------------------------------------------------------------------
// tensor-core knn, register-prefetch pipeline, double-buffered SQ.
// D = Xq @ (-2*Xj)^T  (fp16 split, fp32 accum);  key = D + sq_j
// 512 threads = 16 warps; warp w: GEMM tile (mt=w>>2, nt=w&3),
// selection for queries [w*4, w*4+4).
// ---------------------------------------------------------------------------
__global__ __launch_bounds__(512, 1) void knn_kernel(const float* __restrict__ x) {
    __shared__ __align__(16) __half BH[TJ][BP];     //  9216 B
    __shared__ __align__(16) __half BL[TJ][BP];     //  9216 B
    __shared__ __align__(16) float  Dsh[QB][DP];    // 17408 B (A-stage in prologue)
    __shared__ float SQt[2][TJ];                    //   512 B (double buffered!)
    __shared__ float LK[QB][KNN];                   //  4096 B
    __shared__ int   LI[QB][KNN];                   //  4096 B

    const int tid  = threadIdx.x;
    const int w    = tid >> 5;
    const int lane = tid & 31;
    const int mt   = w >> 2;
    const int nt   = w & 3;
    const int qBase = blockIdx.x * QB;
    const int t16  = lane & 15;
    const int pj   = tid >> 3;        // 0..63  prefetch row
    const int pk   = tid & 7;         // 0..7   prefetch 16B chunk

    // ---- prologue: stage query rows (qhi into Dsh scratch, qlo into BH) ----
    {
        __half* AH = (__half*)&Dsh[0][0];
        __half* AL = (__half*)&BH[0][0];
        const uint4* sh = (const uint4*)(g_qhi + (size_t)(qBase + pj) * C + pk * 8);
        const uint4* sl = (const uint4*)(g_qlo + (size_t)(qBase + pj) * C + pk * 8);
        *((uint4*)(AH + pj * BP + pk * 8)) = *sh;
        *((uint4*)(AL + pj * BP + pk * 8)) = *sl;
    }
    __syncthreads();

    wmma::fragment<wmma::matrix_a, 16, 16, 16, __half, wmma::row_major> a_hi[4], a_lo[4];
    {
        const __half* AH = (const __half*)&Dsh[0][0];
        const __half* AL = (const __half*)&BH[0][0];
        #pragma unroll
        for (int kk = 0; kk < 4; kk++) {
            wmma::load_matrix_sync(a_hi[kk], AH + (mt * 16) * BP + kk * 16, BP);
            wmma::load_matrix_sync(a_lo[kk], AL + (mt * 16) * BP + kk * 16, BP);
        }
    }

    if (lane < KNN) {
        #pragma unroll
        for (int qi = 0; qi < 4; qi++) {
            LK[w * 4 + qi][lane] = FINF;
            LI[w * 4 + qi][lane] = 0;
        }
    }
    float cm[4];
    #pragma unroll
    for (int qi = 0; qi < 4; qi++) cm[qi] = FINF;

    // ---- prefetch tile 0 into registers ------------------------------------
    uint4 pfh = *((const uint4*)(g_hi + (size_t)pj * C + pk * 8));
    uint4 pfl = *((const uint4*)(g_lo + (size_t)pj * C + pk * 8));
    float pfs = (tid < TJ) ? g_sq[tid] : 0.f;

    __syncthreads();   // a_frags loaded; BH scratch free

    // ---- main loop over j-tiles --------------------------------------------
    for (int jt = 0; jt < N; jt += TJ) {
        const int buf = (jt >> 6) & 1;        // TJ = 64
        // commit prefetched tile to smem (BH/BL safe: all warps passed bar2
        // of prev iter, whose GEMM was their last read; SQt uses buf parity)
        *((uint4*)(&BH[pj][pk * 8])) = pfh;
        *((uint4*)(&BL[pj][pk * 8])) = pfl;
        if (tid < TJ) SQt[buf][tid] = pfs;
        __syncthreads();

        // issue next tile's loads (in flight across GEMM + selection)
        {
            int njt = (jt + TJ < N) ? jt + TJ : 0;
            pfh = *((const uint4*)(g_hi + (size_t)(njt + pj) * C + pk * 8));
            pfl = *((const uint4*)(g_lo + (size_t)(njt + pj) * C + pk * 8));
            if (tid < TJ) pfs = g_sq[njt + tid];
        }

        // GEMM: 16x16 tile per warp, 3 split terms x 4 k-steps
        {
            wmma::fragment<wmma::accumulator, 16, 16, 16, float> acc;
            wmma::fill_fragment(acc, 0.f);
            #pragma unroll
            for (int kk = 0; kk < 4; kk++) {
                wmma::fragment<wmma::matrix_b, 16, 16, 16, __half, wmma::col_major> b_hi, b_lo;
                wmma::load_matrix_sync(b_hi, &BH[nt * 16][kk * 16], BP);
                wmma::load_matrix_sync(b_lo, &BL[nt * 16][kk * 16], BP);
                wmma::mma_sync(acc, a_hi[kk], b_hi, acc);
                wmma::mma_sync(acc, a_hi[kk], b_lo, acc);
                wmma::mma_sync(acc, a_lo[kk], b_hi, acc);
            }
            wmma::store_matrix_sync(&Dsh[mt * 16][nt * 16], acc, DP, wmma::mem_row_major);
        }
        __syncthreads();

        // selection: warp w handles queries w*4..w*4+3
        #pragma unroll
        for (int qi = 0; qi < 4; qi++) {
            const int q  = w * 4 + qi;
            const int qg = qBase + q;
            float key[2];
            #pragma unroll
            for (int g = 0; g < 2; g++) {
                int jj = lane + 32 * g;
                key[g] = Dsh[q][jj] + SQt[buf][jj];
                if (jt + jj == qg) key[g] = FINF;      // exclude self
            }
            float kmin = fminf(key[0], key[1]);
            if (__ballot_sync(FULLM, kmin < cm[qi])) {
                #pragma unroll
                for (int g = 0; g < 2; g++) {
                    unsigned bmask = __ballot_sync(FULLM, key[g] < cm[qi]);
                    while (bmask) {
                        int src = __ffs(bmask) - 1;
                        bmask &= bmask - 1;
                        float ck = __shfl_sync(FULLM, key[g], src);
                        int   cj = jt + src + 32 * g;
                        if (ck < cm[qi]) {             // re-check vs updated cm
                            float lv = (lane < KNN) ? LK[q][t16] : -FINF;
                            int   lp = t16;
                            #pragma unroll
                            for (int off = 8; off; off >>= 1) {
                                float ov = __shfl_xor_sync(FULLM, lv, off);
                                int   op = __shfl_xor_sync(FULLM, lp, off);
                                if (ov > lv || (ov == lv && op < lp)) { lv = ov; lp = op; }
                            }
                            int mp = __shfl_sync(FULLM, lp, 0);
                            if (lane == 0) { LK[q][mp] = ck; LI[q][mp] = cj; }
                            __syncwarp(FULLM);
                            float nv = (lane < KNN) ? LK[q][t16] : -FINF;
                            #pragma unroll
                            for (int off = 8; off; off >>= 1)
                                nv = fmaxf(nv, __shfl_xor_sync(FULLM, nv, off));
                            cm[qi] = __shfl_sync(FULLM, nv, 0);
                        }
                    }
                }
            }
        }
    }

    // ---- write out lists (order irrelevant: feeds max-pool) ----------------
    __syncwarp(FULLM);
    if (lane < KNN) {
        #pragma unroll
        for (int qi = 0; qi < 4; qi++)
            g_idx[(qBase + w * 4 + qi) * KNN + lane] = LI[w * 4 + qi][lane];
    }
}

// ---------------------------------------------------------------------------
// out[n, o] = relu(A[n,o] + max_k B[idx[n,k], o]) ; permuted store
// ---------------------------------------------------------------------------
__global__ void out_kernel(float* __restrict__ y) {
    __shared__ int idxs[KNN];
    int n = blockIdx.x;
    int o = threadIdx.x;
    if (o < KNN) idxs[o] = g_idx[n * KNN + o];
    __syncthreads();
    float m = -FINF;
    #pragma unroll
    for (int k = 0; k < KNN; k++)
        m = fmaxf(m, g_B[idxs[k] * O + o]);
    float v = fmaxf(g_A[n * O + o] + m, 0.f);
    y[(n * 4 + (o & 3)) * C + (o >> 2)] = v;
}

// ---------------------------------------------------------------------------
extern "C" void kernel_launch(void* const* d_in, const int* in_sizes, int n_in,
                              void* d_out, int out_size) {
    const float* x = (const float*)d_in[0];
    const float* W = (const float*)d_in[1];
    const float* b = (const float*)d_in[2];
    float* y = (float*)d_out;

    sq_kernel <<<N / 8, 256>>>(x);
    knn_kernel<<<N / QB, 512>>>(x);
    ab_kernel <<<N / NB, 256>>>(x, W, b);
    out_kernel<<<N, 256>>>(y);
}